// round 8
// baseline (speedup 1.0000x reference)
#include <cuda_runtime.h>
#include <cuda_bf16.h>
#include <cstdint>
#include <cstddef>

#define NMAX   500000
#define GQ     128
#define GCELLS (2*GQ*GQ*GQ)
#define KTOP   256
#define NBINS  4096
#define CANDMAX 4096
#define NCOLS  257
#define NTJ    33             // n8 tiles
#define WFRAGN (4*8*32)       // stage-1 B fragments (Wv): 1024 uint2
#define CFRAGN (NTJ*2*32)     // stage-2 B fragments (cols): 2112 uint2
#define GRIDN  148
#define NT     (GRIDN*256)

// ------------------------- scratch (__device__ globals, no allocs) ---------
__device__ int                 g_grid[GCELLS];
__device__ int                 g_owner[NMAX];
__device__ unsigned char       g_peak[NMAX];
__device__ int                 g_hist[NBINS];
__device__ int                 g_thresh;
__device__ int                 g_candcnt;
__device__ int                 g_touchcnt;
__device__ unsigned long long  g_ckey[CANDMAX];
__device__ float               g_conf[KTOP];
__device__ int                 g_topidx[KTOP];
__device__ int                 g_touched[2048];
__device__ float               g_sums[KTOP*128];
__device__ float               g_counts[KTOP];
__device__ float               g_cols[NCOLS*32];
__device__ uint2               g_wfH[WFRAGN];
__device__ uint2               g_wfL[WFRAGN];
__device__ uint2               g_cfH[CFRAGN];
__device__ uint2               g_cfL[CFRAGN];
__device__ unsigned            g_syncc;          // grid barrier counter (monotonic)

// ------------------------- helpers ----------------------------------------
__device__ __forceinline__ uint32_t pack_bf16(float lo, float hi) {
    uint32_t r;
    asm("cvt.rn.bf16x2.f32 %0, %1, %2;" : "=r"(r) : "f"(hi), "f"(lo));
    return r;
}
__device__ __forceinline__ float bf16_lo_f(uint32_t p) {
    __nv_bfloat16 h = __ushort_as_bfloat16((unsigned short)(p & 0xFFFFu));
    return __bfloat162float(h);
}
__device__ __forceinline__ float bf16_hi_f(uint32_t p) {
    __nv_bfloat16 h = __ushort_as_bfloat16((unsigned short)(p >> 16));
    return __bfloat162float(h);
}
__device__ __forceinline__ void mma_bf16(float* c, const uint32_t* a,
                                         uint32_t b0, uint32_t b1)
{
    asm volatile(
        "mma.sync.aligned.m16n8k16.row.col.f32.bf16.bf16.f32 "
        "{%0,%1,%2,%3}, {%4,%5,%6,%7}, {%8,%9}, {%0,%1,%2,%3};"
        : "+f"(c[0]), "+f"(c[1]), "+f"(c[2]), "+f"(c[3])
        : "r"(a[0]), "r"(a[1]), "r"(a[2]), "r"(a[3]), "r"(b0), "r"(b1));
}

// grid-wide barrier: monotonic counter, wrap-safe, replay-safe (no reset)
__device__ __forceinline__ void gridbar()
{
    __syncthreads();
    if (threadIdx.x == 0) {
        __threadfence();
        unsigned old = atomicAdd(&g_syncc, 1u);
        unsigned target = old - (old % GRIDN) + GRIDN;
        while ((int)(atomicAdd(&g_syncc, 0u) - target) < 0) __nanosleep(64);
        __threadfence();
    }
    __syncthreads();
}

// ------------------------- fused sparse pipeline (148 x 256, coresident) --
__global__ void __launch_bounds__(256, 1)
k_sparse(const int* __restrict__ coords, const float* __restrict__ feats,
         const float* __restrict__ scores, const float* __restrict__ Wv,
         const float* __restrict__ Wc, const float* __restrict__ bc,
         const float* __restrict__ bg, float* conf_out, int n)
{
    __shared__ unsigned long long sbuf64[CANDMAX];   // 32 KB (hist/sort reuse)
    __shared__ int sup[64];
    int t = threadIdx.x;
    int gtid = blockIdx.x * 256 + t;

    // ---- P0: clears + Wv fragments ----
    int4 m1 = make_int4(-1, -1, -1, -1);
    for (int i = gtid; i < GCELLS/4; i += NT) ((int4*)g_grid)[i] = m1;
    for (int i = gtid; i < NMAX/4;   i += NT) ((int4*)g_owner)[i] = m1;
    for (int i = gtid; i < NBINS;    i += NT) g_hist[i] = 0;
    for (int i = gtid; i < KTOP*128; i += NT) g_sums[i] = 0.0f;
    for (int i = gtid; i < KTOP;     i += NT) g_counts[i] = 0.0f;
    if (gtid == 0) { g_candcnt = 0; g_touchcnt = 0; }
    if (gtid < WFRAGN) {
        int idx = gtid;
        int l  = idx & 31;
        int kt = (idx >> 5) & 7;
        int j  = idx >> 8;
        int d  = j*8 + (l >> 2);
        int k0 = kt*16 + 2*(l & 3);
        float w0 = Wv[(k0  )*32 + d], w1 = Wv[(k0+1)*32 + d];
        float w2 = Wv[(k0+8)*32 + d], w3 = Wv[(k0+9)*32 + d];
        uint32_t hx = pack_bf16(w0, w1), hy = pack_bf16(w2, w3);
        uint32_t lx = pack_bf16(w0 - bf16_lo_f(hx), w1 - bf16_hi_f(hx));
        uint32_t ly = pack_bf16(w2 - bf16_lo_f(hy), w3 - bf16_hi_f(hy));
        g_wfH[idx] = make_uint2(hx, hy);
        g_wfL[idx] = make_uint2(lx, ly);
    }
    gridbar();  // 1

    // ---- P1: fill grid ----
    for (int i = gtid; i < n; i += NT) {
        int4 c = ((const int4*)coords)[i];
        g_grid[((c.x*GQ + c.y)*GQ + c.z)*GQ + c.w] = i;
    }
    gridbar();  // 2

    // ---- P2: peak detection + histogram ----
    for (int i = gtid; i < n; i += NT) {
        float s = scores[i];
        bool pk = false;
        if (s > 0.1f) {
            float nm = -1e30f;
            int4 c = ((const int4*)coords)[i];
            const int dx[7] = {0, 1,-1, 0, 0, 0, 0};
            const int dy[7] = {0, 0, 0, 1,-1, 0, 0};
            const int dz[7] = {0, 0, 0, 0, 0, 1,-1};
            #pragma unroll
            for (int o = 0; o < 7; ++o) {
                int nx = c.y + dx[o], ny = c.z + dy[o], nz = c.w + dz[o];
                if (nx < 0 || nx >= GQ || ny < 0 || ny >= GQ || nz < 0 || nz >= GQ) continue;
                int j = g_grid[((c.x*GQ + nx)*GQ + ny)*GQ + nz];
                if (j >= 0) {
                    float sj = scores[j];
                    if (sj > 0.1f) nm = fmaxf(nm, sj);
                }
            }
            pk = (s >= nm - 1e-6f) && (s >= 0.5f);
        }
        g_peak[i] = pk ? 1 : 0;
        if (pk) {
            int b = (int)((s - 0.5f) * 8192.0f);
            b = b < 0 ? 0 : (b > NBINS-1 ? NBINS-1 : b);
            atomicAdd(&g_hist[b], 1);
        }
    }
    gridbar();  // 3

    // ---- P3: threshold scan (block 0) ----
    if (blockIdx.x == 0) {
        int* h = (int*)sbuf64;
        for (int i = t; i < NBINS; i += 256) h[i] = g_hist[i];
        __syncthreads();
        if (t < 64) {
            int s = 0;
            for (int m = 0; m < 64; ++m) s += h[t*64 + m];
            sup[t] = s;
        }
        __syncthreads();
        if (t == 0) {
            int total = 0;
            for (int s = 0; s < 64; ++s) total += sup[s];
            int target = total < KTOP ? total : KTOP;
            int T = 0;
            if (target > 0) {
                int acc = 0, sb = 63;
                for (; sb >= 0; --sb) {
                    if (acc + sup[sb] >= target) break;
                    acc += sup[sb];
                }
                for (int b = 63; b >= 0; --b) {
                    acc += h[sb*64 + b];
                    if (acc >= target) { T = sb*64 + b; break; }
                }
            }
            g_thresh = T;
        }
        __syncthreads();
    }
    gridbar();  // 4

    // ---- P4: collect candidates ----
    for (int i = gtid; i < n; i += NT) {
        if (!g_peak[i]) continue;
        float s = scores[i];
        int b = (int)((s - 0.5f) * 8192.0f);
        b = b < 0 ? 0 : (b > NBINS-1 ? NBINS-1 : b);
        if (b >= g_thresh) {
            int pos = atomicAdd(&g_candcnt, 1);
            if (pos < CANDMAX) {
                unsigned long long key =
                    ((unsigned long long)__float_as_uint(s) << 32)
                  | (unsigned long long)(0xFFFFFFFFu - (unsigned)i);
                g_ckey[pos] = key;
            }
        }
    }
    gridbar();  // 5

    // ---- P5: bitonic top-256 + owner assignment (block 0) ----
    if (blockIdx.x == 0) {
        unsigned long long* sk = sbuf64;
        int cnt = g_candcnt;
        if (cnt > CANDMAX) cnt = CANDMAX;
        int S = 256;
        while (S < cnt) S <<= 1;
        for (int i = t; i < S; i += 256) sk[i] = (i < cnt) ? g_ckey[i] : 0ULL;
        __syncthreads();
        for (int k = 2; k <= S; k <<= 1) {
            for (int j = k >> 1; j > 0; j >>= 1) {
                for (int i = t; i < S; i += 256) {
                    int ixj = i ^ j;
                    if (ixj > i) {
                        unsigned long long a = sk[i], b = sk[ixj];
                        bool sw = ((i & k) == 0) ? (a < b) : (a > b);
                        if (sw) { sk[i] = b; sk[ixj] = a; }
                    }
                }
                __syncthreads();
            }
        }
        {
            bool valid = t < cnt;
            unsigned long long key = sk[t];
            float sc = valid ? __uint_as_float((unsigned)(key >> 32)) : 0.0f;
            g_conf[t] = sc;
            g_topidx[t] = valid ? (int)(0xFFFFFFFFu - (unsigned)(key & 0xFFFFFFFFULL)) : -1;
            if (conf_out) conf_out[t] = sc;
        }
        __syncthreads();
        // owner assignment (t = peak rank)
        int p = g_topidx[t];
        if (p >= 0) {
            int4 c = ((const int4*)coords)[p];
            const int dx[7] = {0, 1,-1, 0, 0, 0, 0};
            const int dy[7] = {0, 0, 0, 1,-1, 0, 0};
            const int dz[7] = {0, 0, 0, 0, 0, 1,-1};
            #pragma unroll
            for (int o = 0; o < 7; ++o) {
                int nx = c.y + dx[o], ny = c.z + dy[o], nz = c.w + dz[o];
                if (nx < 0 || nx >= GQ || ny < 0 || ny >= GQ || nz < 0 || nz >= GQ) continue;
                int j = g_grid[((c.x*GQ + nx)*GQ + ny)*GQ + nz];
                if (j >= 0 && scores[j] > 0.1f) {
                    int old = atomicMax(&g_owner[j], t);
                    if (old == -1) {
                        int pos = atomicAdd(&g_touchcnt, 1);
                        g_touched[pos] = j;
                    }
                }
            }
        }
    }
    gridbar();  // 6

    // ---- P6: segment sums ----
    {
        int touch = g_touchcnt;
        for (int i = gtid; i < touch*128; i += NT) {
            int v = g_touched[i >> 7];
            int o = g_owner[v];
            atomicAdd(&g_sums[o*128 + (i & 127)], feats[(size_t)v*128 + (i & 127)]);
        }
        for (int i = gtid; i < touch; i += NT)
            atomicAdd(&g_counts[g_owner[g_touched[i]]], 1.0f);
    }
    gridbar();  // 7

    // ---- P7: build cols (one warp per (c,d)) ----
    {
        int wg = gtid >> 5, lane = gtid & 31;
        for (int w = wg; w < NCOLS*32; w += NT/32) {
            int c = w >> 5, d = w & 31;
            if (c == 0) {
                if (lane == 0) g_cols[d] = bg[d];
                continue;
            }
            int seg = c - 1;
            float inv = 1.0f / fmaxf(g_counts[seg], 1.0f);
            float s = 0.0f;
            #pragma unroll
            for (int q = 0; q < 4; ++q) {
                int m = lane + q*32;
                s += g_sums[seg*128 + m] * Wc[m*32 + d];
            }
            #pragma unroll
            for (int o = 16; o > 0; o >>= 1)
                s += __shfl_down_sync(0xFFFFFFFFu, s, o);
            if (lane == 0)
                g_cols[c*32 + d] = g_conf[seg] * (bc[d] + s * inv);
        }
    }
    gridbar();  // 8

    // ---- P8: cols fragments ----
    for (int idx = gtid; idx < CFRAGN; idx += NT) {
        int l  = idx & 31;
        int kt = (idx >> 5) & 1;
        int j  = idx >> 6;
        int c  = j*8 + (l >> 2);
        int k0 = kt*16 + 2*(l & 3);
        float w0 = 0.f, w1 = 0.f, w2 = 0.f, w3 = 0.f;
        if (c < NCOLS) {
            const float* row = g_cols + c*32;
            w0 = row[k0]; w1 = row[k0+1]; w2 = row[k0+8]; w3 = row[k0+9];
        }
        uint32_t hx = pack_bf16(w0, w1), hy = pack_bf16(w2, w3);
        uint32_t lx = pack_bf16(w0 - bf16_lo_f(hx), w1 - bf16_hi_f(hx));
        uint32_t ly = pack_bf16(w2 - bf16_lo_f(hy), w3 - bf16_hi_f(hy));
        g_cfH[idx] = make_uint2(hx, hy);
        g_cfL[idx] = make_uint2(lx, ly);
    }
}

// ------------------------- persistent two-stage mma.sync GEMM -------------
// smem: wfH 8192 | wfL 8192 | cfH 16896 | cfL 16896 | bv 128  = 50304 B
#define SM_WH   0
#define SM_WL   8192
#define SM_CH   16384
#define SM_CL   33280
#define SM_BV   50176
#define SM_TOT  50304

__global__ void __launch_bounds__(256, 2)
k_gemm(const float* __restrict__ A, const float* __restrict__ bv,
       float* __restrict__ outI, int n, int ntiles)
{
    extern __shared__ char smraw[];
    uint2* sWH = (uint2*)(smraw + SM_WH);
    uint2* sWL = (uint2*)(smraw + SM_WL);
    uint2* sCH = (uint2*)(smraw + SM_CH);
    uint2* sCL = (uint2*)(smraw + SM_CL);
    float* sBV = (float*)(smraw + SM_BV);

    int t   = threadIdx.x;
    int wid = t >> 5;
    int l   = t & 31;

    for (int i = t; i < WFRAGN; i += 256) { sWH[i] = g_wfH[i]; sWL[i] = g_wfL[i]; }
    for (int i = t; i < CFRAGN; i += 256) { sCH[i] = g_cfH[i]; sCL[i] = g_cfL[i]; }
    if (t < 32) sBV[t] = bv[t];
    __syncthreads();

    int lq = l >> 2;           // 0..7
    int lr = l & 3;            // 0..3

    for (int tile = blockIdx.x; tile < ntiles; tile += gridDim.x) {
        int rowbase = tile * 128 + wid * 16;
        int r0 = rowbase + lq;
        int r1 = r0 + 8;
        bool ok0 = r0 < n, ok1 = r1 < n;

        // ---- load A fragments from global, split hi/lo ----
        uint32_t ahi[8][4], alo[8][4];
        #pragma unroll
        for (int kt = 0; kt < 8; ++kt) {
            int k0 = kt*16 + 2*lr;
            float2 p00 = make_float2(0.f, 0.f), p10 = p00, p01 = p00, p11 = p00;
            if (ok0) {
                p00 = *(const float2*)(A + (size_t)r0*128 + k0);
                p01 = *(const float2*)(A + (size_t)r0*128 + k0 + 8);
            }
            if (ok1) {
                p10 = *(const float2*)(A + (size_t)r1*128 + k0);
                p11 = *(const float2*)(A + (size_t)r1*128 + k0 + 8);
            }
            uint32_t h;
            h = pack_bf16(p00.x, p00.y); ahi[kt][0] = h;
            alo[kt][0] = pack_bf16(p00.x - bf16_lo_f(h), p00.y - bf16_hi_f(h));
            h = pack_bf16(p10.x, p10.y); ahi[kt][1] = h;
            alo[kt][1] = pack_bf16(p10.x - bf16_lo_f(h), p10.y - bf16_hi_f(h));
            h = pack_bf16(p01.x, p01.y); ahi[kt][2] = h;
            alo[kt][2] = pack_bf16(p01.x - bf16_lo_f(h), p01.y - bf16_hi_f(h));
            h = pack_bf16(p11.x, p11.y); ahi[kt][3] = h;
            alo[kt][3] = pack_bf16(p11.x - bf16_lo_f(h), p11.y - bf16_hi_f(h));
        }

        // ---- stage 1: desc = A @ Wv (4 n8-tiles over d) ----
        float dsc[4][4];
        #pragma unroll
        for (int j = 0; j < 4; ++j) {
            float acc[4] = {0.f, 0.f, 0.f, 0.f};
            #pragma unroll
            for (int kt = 0; kt < 8; ++kt) {
                uint2 bh = sWH[(j*8 + kt)*32 + l];
                uint2 bl = sWL[(j*8 + kt)*32 + l];
                mma_bf16(acc, ahi[kt], bh.x, bh.y);
                mma_bf16(acc, alo[kt], bh.x, bh.y);
                mma_bf16(acc, ahi[kt], bl.x, bl.y);
            }
            dsc[j][0] = acc[0]; dsc[j][1] = acc[1];
            dsc[j][2] = acc[2]; dsc[j][3] = acc[3];
        }

        // ---- add bv, split, compose into stage-2 A fragments ----
        uint32_t dhi[2][4], dlo[2][4];
        #pragma unroll
        for (int kt = 0; kt < 2; ++kt) {
            #pragma unroll
            for (int hfl = 0; hfl < 2; ++hfl) {
                int j = 2*kt + hfl;
                float b0 = sBV[j*8 + 2*lr];
                float b1 = sBV[j*8 + 2*lr + 1];
                float v0 = dsc[j][0] + b0, v1 = dsc[j][1] + b1;
                float v2 = dsc[j][2] + b0, v3 = dsc[j][3] + b1;
                uint32_t h01 = pack_bf16(v0, v1);
                uint32_t h23 = pack_bf16(v2, v3);
                dhi[kt][2*hfl+0] = h01;
                dhi[kt][2*hfl+1] = h23;
                dlo[kt][2*hfl+0] = pack_bf16(v0 - bf16_lo_f(h01), v1 - bf16_hi_f(h01));
                dlo[kt][2*hfl+1] = pack_bf16(v2 - bf16_lo_f(h23), v3 - bf16_hi_f(h23));
            }
        }

        // ---- stage 2: out = desc @ cols^T (33 n8-tiles) ----
        #pragma unroll 1
        for (int j = 0; j < NTJ; ++j) {
            float acc[4] = {0.f, 0.f, 0.f, 0.f};
            #pragma unroll
            for (int kt = 0; kt < 2; ++kt) {
                uint2 bh = sCH[(j*2 + kt)*32 + l];
                uint2 bl = sCL[(j*2 + kt)*32 + l];
                mma_bf16(acc, dhi[kt], bh.x, bh.y);
                mma_bf16(acc, dlo[kt], bh.x, bh.y);
                mma_bf16(acc, dhi[kt], bl.x, bl.y);
            }
            int n0 = j*8 + 2*lr;
            if (j < NTJ - 1) {
                if (ok0) {
                    float* op = outI + (size_t)r0*NCOLS + n0;
                    op[0] = acc[0]; op[1] = acc[1];
                }
                if (ok1) {
                    float* op = outI + (size_t)r1*NCOLS + n0;
                    op[0] = acc[2]; op[1] = acc[3];
                }
            } else {
                if (n0 == 256) {
                    if (ok0) outI[(size_t)r0*NCOLS + 256] = acc[0];
                    if (ok1) outI[(size_t)r1*NCOLS + 256] = acc[2];
                }
            }
        }
    }
}

// ------------------------- launch -----------------------------------------
extern "C" void kernel_launch(void* const* d_in, const int* in_sizes, int n_in,
                              void* d_out, int out_size)
{
    const int*   coords = (const int*)  d_in[0];
    const float* feats  = (const float*)d_in[1];
    const float* scores = (const float*)d_in[2];
    const float* Wv     = (const float*)d_in[3];
    const float* bv     = (const float*)d_in[4];
    const float* Wc     = (const float*)d_in[5];
    const float* bc     = (const float*)d_in[6];
    const float* bg     = (const float*)d_in[7];

    int n = in_sizes[0] / 4;
    if (n > NMAX) n = NMAX;

    float* out = (float*)d_out;
    long long inst = (long long)n * NCOLS;
    int off = (int)((long long)out_size - inst);   // expect 256 (conf first)
    if (off < 0) off = 0;
    float* conf_out = (off >= KTOP) ? out : nullptr;
    float* inst_out = out + off;

    cudaFuncSetAttribute(k_gemm, cudaFuncAttributeMaxDynamicSharedMemorySize, SM_TOT);

    k_sparse<<<GRIDN, 256>>>(coords, feats, scores, Wv, Wc, bc, bg, conf_out, n);

    int ntiles = (n + 127) / 128;
    k_gemm<<<296, 256, SM_TOT>>>(feats, bv, inst_out, n, ntiles);
}